// round 11
// baseline (speedup 1.0000x reference)
#include <cuda_runtime.h>
#include <math.h>

#define TFv  8192
#define TF2v 4096
#define TPv  512
#define Bv   16
#define EPSv 1e-8f

// Scratch (no allocations allowed -> device globals)
__device__ float g_d2pair[Bv * TF2v];
__device__ float g_f0pair[Bv * TF2v];
__device__ unsigned g_ctr = 0;   // last-block-does-tail counter (self-resetting)

// ---------------------------------------------------------------------------
// Kernel 1: segment-parallel frame pipeline (unchanged; ~4.6us).
// ---------------------------------------------------------------------------
#define SEG   256
#define HALO  128
#define EXTN  512
#define ABASE 120
#define ASZ   272

__global__ void __launch_bounds__(256) frame_kernel(const float* __restrict__ f0g) {
    __shared__ float s_f0[EXTN];
    __shared__ float s_a[ASZ];
    __shared__ float s_b[ASZ];
    __shared__ int   s_prev[EXTN];
    __shared__ int   s_next[EXTN];
    __shared__ int   s_wA[8], s_wB[8];
    __shared__ int   s_seed[2];

    const int blk   = blockIdx.x;
    const int b     = blk >> 5;
    const int seg   = blk & 31;
    const int start = seg * SEG;
    const int EB    = start - HALO;
    const int tid   = threadIdx.x;
    const int lane  = tid & 31;
    const int warp  = tid >> 5;
    const unsigned FULL = 0xffffffffu;
    const float* __restrict__ f0row = f0g + (size_t)b * TFv;

    #pragma unroll
    for (int i = tid; i < EXTN; i += 256) {
        int g = EB + i;
        int gc = g < 0 ? 0 : (g > TFv - 1 ? TFv - 1 : g);
        s_f0[i] = f0row[gc];
    }

    if (warp == 0) {
        int found = -1;
        for (int g0 = EB - 1; g0 >= 0 && found < 0; g0 -= 32) {
            int g = g0 - lane;
            bool v = (g >= 0) && (f0row[g] > 0.0f);
            unsigned m = __ballot_sync(FULL, v);
            if (m) found = g0 - (__ffs(m) - 1);
        }
        if (lane == 0) s_seed[0] = found;
    } else if (warp == 1) {
        int found = TFv;
        for (int g0 = EB + EXTN; g0 < TFv && found == TFv; g0 += 32) {
            int g = g0 + lane;
            bool v = (g < TFv) && (f0row[g] > 0.0f);
            unsigned m = __ballot_sync(FULL, v);
            if (m) found = g0 + (__ffs(m) - 1);
        }
        if (lane == 0) s_seed[1] = found;
    }
    __syncthreads();

    const int li0 = 2 * tid;
    const int g0i = EB + li0;

    int run = -1;
    if (s_f0[li0]     > 0.0f) run = g0i;
    s_prev[li0] = run;
    if (s_f0[li0 + 1] > 0.0f) run = g0i + 1;
    s_prev[li0 + 1] = run;
    int v = run;
    #pragma unroll
    for (int off = 1; off < 32; off <<= 1) {
        int u = __shfl_up_sync(FULL, v, off);
        if (lane >= off && u > v) v = u;
    }
    if (lane == 31) s_wA[warp] = v;
    __syncthreads();
    if (warp == 0 && lane < 8) {
        int x = s_wA[lane];
        #pragma unroll
        for (int off = 1; off < 8; off <<= 1) {
            int u = __shfl_up_sync(0xffu, x, off);
            if (lane >= off && u > x) x = u;
        }
        s_wA[lane] = x;
    }
    __syncthreads();
    {
        int wpre = (warp > 0) ? s_wA[warp - 1] : -1;
        int lp = __shfl_up_sync(FULL, v, 1);
        int epre = (lane > 0) ? lp : -1;
        int pre = (wpre > epre) ? wpre : epre;
        int sd = s_seed[0];
        if (sd > pre) pre = sd;
        if (s_prev[li0]     < pre) s_prev[li0]     = pre;
        int pre1 = (s_prev[li0] > pre) ? s_prev[li0] : pre;
        if (s_prev[li0 + 1] < pre1) s_prev[li0 + 1] = pre1;
    }

    int runn = TFv;
    if (s_f0[li0 + 1] > 0.0f) runn = g0i + 1;
    s_next[li0 + 1] = runn;
    if (s_f0[li0]     > 0.0f) runn = g0i;
    s_next[li0] = runn;
    int v2 = runn;
    #pragma unroll
    for (int off = 1; off < 32; off <<= 1) {
        int u = __shfl_down_sync(FULL, v2, off);
        if (lane + off < 32 && u < v2) v2 = u;
    }
    if (lane == 0) s_wB[warp] = v2;
    __syncthreads();
    if (warp == 0 && lane < 8) {
        int x = s_wB[lane];
        #pragma unroll
        for (int off = 1; off < 8; off <<= 1) {
            int u = __shfl_down_sync(0xffu, x, off);
            if (lane + off < 8 && u < x) x = u;
        }
        s_wB[lane] = x;
    }
    __syncthreads();
    {
        int wsuf = (warp < 7) ? s_wB[warp + 1] : TFv;
        int ln = __shfl_down_sync(FULL, v2, 1);
        int esuf = (lane < 31) ? ln : TFv;
        int suf = (wsuf < esuf) ? wsuf : esuf;
        int sd = s_seed[1];
        if (sd < suf) suf = sd;
        if (s_next[li0 + 1] > suf) s_next[li0 + 1] = suf;
        int suf0 = (s_next[li0 + 1] < suf) ? s_next[li0 + 1] : suf;
        if (s_next[li0] > suf0) s_next[li0] = suf0;
    }
    __syncthreads();

    #pragma unroll
    for (int i = tid; i < ASZ; i += 256) {
        int t = EB + ABASE + i;
        if (t < 0 || t >= TFv) continue;
        int li = ABASE + i;
        float f = s_f0[li];
        if (f > 0.0f) {
            s_a[i] = f;
        } else {
            int lo = s_prev[li], hi = s_next[li];
            int lo_t = (lo >= 0)  ? lo : hi;
            int hi_t = (hi < TFv) ? hi : lo;
            float lov = f0row[lo_t];
            float hiv = f0row[hi_t];
            int sp = hi_t - lo_t; if (sp < 1) sp = 1;
            float w = ((float)t - (float)lo_t) / (float)sp;
            w = fminf(fmaxf(w, 0.0f), 1.0f);
            s_a[i] = lov + w * (hiv - lov);
        }
    }
    __syncthreads();

    {
        const float c0 = -2.0f / 21.0f, c1 = 3.0f / 21.0f, c2 = 6.0f / 21.0f, c3 = 7.0f / 21.0f;
        #pragma unroll
        for (int i = 7 + tid; i < 265; i += 256) {
            int t = (start - 8) + i;
            int m1 = t-1 > 0 ? t-1 : 0;
            int m2 = t-2 > 0 ? t-2 : 0;
            int m3 = t-3 > 0 ? t-3 : 0;
            int p1 = t+1 < TFv-1 ? t+1 : TFv-1;
            int p2 = t+2 < TFv-1 ? t+2 : TFv-1;
            int p3 = t+3 < TFv-1 ? t+3 : TFv-1;
            int off = start - 8;
            s_b[i] = c3 * s_a[t - off]
                   + c2 * (s_a[m1 - off] + s_a[p1 - off])
                   + c1 * (s_a[m2 - off] + s_a[p2 - off])
                   + c0 * (s_a[m3 - off] + s_a[p3 - off]);
        }
    }
    __syncthreads();

    if (tid < 128) {
        int j  = (start >> 1) + tid;
        int t0 = 2 * j, t1 = t0 + 1;
        int t0m = t0 - 1 > 0 ? t0 - 1 : 0;
        int t1p = t1 + 1 < TFv - 1 ? t1 + 1 : TFv - 1;
        int off = start - 8;
        float b0 = s_b[t0 - off], b1 = s_b[t1 - off];
        float d0 = fabsf(s_b[t0m - off] - 2.0f * b0 + b1);
        float d1 = fabsf(b0 - 2.0f * b1 + s_b[t1p - off]);
        g_d2pair[b * TF2v + j] = d0 + d1;
        g_f0pair[b * TF2v + j] = s_f0[(t0 - EB)] + s_f0[(t1 - EB)];
    }
}

// ---------------------------------------------------------------------------
// Kernel 2: heavy kernel + fused tail.
// RPB 16 -> 8: grid 512 -> 1024 (~6 CTAs/SM instead of 3.5; grid was the
// occupancy limiter). __launch_bounds__(256, 6) keeps regs <= 42 so 6 CTAs
// fit the register file. Tables in smem, 2-row ILP, __ldcs streaming loads.
// ---------------------------------------------------------------------------
#define RPB 8
__global__ void __launch_bounds__(256, 6) row_kernel(const float* __restrict__ attn,
                                                     const float* __restrict__ uv,
                                                     float* __restrict__ out) {
    const int blk = blockIdx.x;            // 0 .. 1023
    const int b   = blk >> 6;              // 64 row-groups per batch
    const int rg  = blk & 63;
    const int tid = threadIdx.x;
    const int w   = tid >> 5, l = tid & 31;

    __shared__ float4 s_d[TF2v / 4];       // 16 KB
    __shared__ float4 s_f[TF2v / 4];       // 16 KB
    __shared__ float  red[RPB][3][8];
    __shared__ int    s_last;
    __shared__ float  s_e[Bv];

    {
        const float4* __restrict__ d2p = (const float4*)g_d2pair + (size_t)b * (TF2v / 4);
        const float4* __restrict__ f0p = (const float4*)g_f0pair + (size_t)b * (TF2v / 4);
        #pragma unroll
        for (int i = tid; i < TF2v / 4; i += 256) {
            s_d[i] = d2p[i];
            s_f[i] = f0p[i];
        }
    }
    __syncthreads();

    const float4* __restrict__ base =
        (const float4*)attn + ((size_t)(b * TPv + rg * RPB)) * (TF2v / 4);

    for (int rp = 0; rp < RPB; rp += 2) {
        const float4* __restrict__ row0 = base + (size_t)rp * (TF2v / 4);
        const float4* __restrict__ row1 = row0 + (TF2v / 4);
        float sa0 = 0.f, sc0 = 0.f, sm0 = 0.f;
        float sa1 = 0.f, sc1 = 0.f, sm1 = 0.f;
        #pragma unroll
        for (int k = 0; k < 4; ++k) {
            int idx = tid + 256 * k;
            float4 a0 = __ldcs(&row0[idx]);
            float4 a1 = __ldcs(&row1[idx]);
            float4 d  = s_d[idx];
            float4 f  = s_f[idx];
            sa0 += (a0.x + a0.y) + (a0.z + a0.w);
            sc0 += a0.x * d.x + a0.y * d.y + a0.z * d.z + a0.w * d.w;
            sm0 += a0.x * f.x + a0.y * f.y + a0.z * f.z + a0.w * f.w;
            sa1 += (a1.x + a1.y) + (a1.z + a1.w);
            sc1 += a1.x * d.x + a1.y * d.y + a1.z * d.z + a1.w * d.w;
            sm1 += a1.x * f.x + a1.y * f.y + a1.z * f.z + a1.w * f.w;
        }
        #pragma unroll
        for (int o = 16; o > 0; o >>= 1) {
            sa0 += __shfl_down_sync(0xffffffffu, sa0, o);
            sc0 += __shfl_down_sync(0xffffffffu, sc0, o);
            sm0 += __shfl_down_sync(0xffffffffu, sm0, o);
            sa1 += __shfl_down_sync(0xffffffffu, sa1, o);
            sc1 += __shfl_down_sync(0xffffffffu, sc1, o);
            sm1 += __shfl_down_sync(0xffffffffu, sm1, o);
        }
        if (l == 0) {
            red[rp][0][w]     = sa0; red[rp][1][w]     = sc0; red[rp][2][w]     = sm0;
            red[rp + 1][0][w] = sa1; red[rp + 1][1][w] = sc1; red[rp + 1][2][w] = sm1;
        }
    }
    __syncthreads();

    if (tid < RPB) {
        float sa = 0.0f, sc = 0.0f, sm = 0.0f;
        #pragma unroll
        for (int i = 0; i < 8; ++i) {
            sa += red[tid][0][i]; sc += red[tid][1][i]; sm += red[tid][2][i];
        }
        float denom = fmaxf(2.0f * sa, 1.0f);
        float inv   = 1.0f / (denom + EPSv);
        int bid = b * TPv + rg * RPB + tid;
        out[bid]            = sc * inv;   // curv_phn
        out[Bv * TPv + bid] = sm * inv;   // mean_phn
    }

    // ---- last-block epilogue ----
    __threadfence();
    __syncthreads();
    if (tid == 0) {
        unsigned old = atomicAdd(&g_ctr, 1u);
        s_last = (old == (unsigned)(gridDim.x - 1)) ? 1 : 0;
    }
    __syncthreads();
    if (!s_last) return;
    if (tid == 0) g_ctr = 0;
    __threadfence();

    const float OODM =  21.688259064691245f;   // 12*log2(350/100)
    const float OODC = -71.589411415945055f;   // 12*log2(1.6/100)

    #pragma unroll
    for (int pass = 0; pass < 2; ++pass) {
        int bb = w + 8 * pass;
        float dm = 0.0f, vm = 0.0f, dc = 0.0f, vc = 0.0f;
        #pragma unroll
        for (int k = 0; k < TPv / 32; ++k) {
            int p = l + 32 * k;
            float u  = uv[bb * TPv + p];
            float cv = out[bb * TPv + p];
            float mv = out[Bv * TPv + bb * TPv + p];

            float pvm = mv * u;
            float vmi = (pvm != 0.0f) ? 1.0f : 0.0f;
            float semim = 12.0f * log2f(fmaxf(pvm, 1e-6f) * 0.01f);
            dm += fmaxf(OODM - semim, 0.0f) * vmi;
            vm += vmi;

            float pvc = cv * u;
            float vci = (pvc != 0.0f) ? 1.0f : 0.0f;
            float semic = 12.0f * log2f(fmaxf(pvc, 1e-6f) * 0.01f);
            dc += fmaxf(OODC - semic, 0.0f) * vci;
            vc += vci;
        }
        #pragma unroll
        for (int o = 16; o > 0; o >>= 1) {
            dm += __shfl_down_sync(0xffffffffu, dm, o);
            vm += __shfl_down_sync(0xffffffffu, vm, o);
            dc += __shfl_down_sync(0xffffffffu, dc, o);
            vc += __shfl_down_sync(0xffffffffu, vc, o);
        }
        if (l == 0) s_e[bb] = dm / fmaxf(vm, 1.0f) + dc / fmaxf(vc, 1.0f);
    }
    __syncthreads();

    if (tid == 0) {
        float e[Bv];
        float m = 0.0f;
        #pragma unroll
        for (int i = 0; i < Bv; ++i) { e[i] = s_e[i]; m += e[i]; }
        m /= (float)Bv;
        float var = 0.0f;
        #pragma unroll
        for (int i = 0; i < Bv; ++i) { float dd = e[i] - m; var += dd * dd; }
        var /= (float)Bv;
        float sd = fmaxf(sqrtf(var), 1e-6f);
        float x[Bv], mx = -1e30f;
        #pragma unroll
        for (int i = 0; i < Bv; ++i) { x[i] = -(e[i] - m) / sd; mx = fmaxf(mx, x[i]); }
        float s = 0.0f;
        #pragma unroll
        for (int i = 0; i < Bv; ++i) { x[i] = expf(x[i] - mx); s += x[i]; }
        float s2 = 0.0f;
        #pragma unroll
        for (int i = 0; i < Bv; ++i) { float wv = x[i] / s; x[i] = wv; s2 += wv * wv; }
        #pragma unroll
        for (int i = 0; i < Bv; ++i) out[2 * Bv * TPv + i] = (float)Bv * x[i];
        out[2 * Bv * TPv + Bv] = 1.0f / s2;
    }
}

// ---------------------------------------------------------------------------

extern "C" void kernel_launch(void* const* d_in, const int* in_sizes, int n_in,
                              void* d_out, int out_size) {
    const float* f0   = (const float*)d_in[0];   // [B, TF]
    const float* attn = (const float*)d_in[1];   // [B, TP, TF2]
    const float* uv   = (const float*)d_in[2];   // [B, TP]
    float* out = (float*)d_out;                  // curv | mean | B*wts | ess

    frame_kernel<<<Bv * 32, 256>>>(f0);
    row_kernel<<<(Bv * TPv) / RPB, 256>>>(attn, uv, out);
}

// round 14
// speedup vs baseline: 1.0059x; 1.0059x over previous
#include <cuda_runtime.h>
#include <math.h>

#define TFv  8192
#define TF2v 4096
#define TPv  512
#define Bv   16
#define EPSv 1e-8f

// Scratch (no allocations allowed -> device globals)
__device__ float g_d2pair[Bv * TF2v];
__device__ float g_f0pair[Bv * TF2v];
__device__ unsigned g_ctr = 0;   // last-block-does-tail counter (self-resetting)

// ---------------------------------------------------------------------------
// mbarrier / bulk-copy helpers
// ---------------------------------------------------------------------------
__device__ __forceinline__ unsigned smem_u32(const void* p) {
    return (unsigned)__cvta_generic_to_shared(p);
}

#define MB_INIT(addr, cnt) \
    asm volatile("mbarrier.init.shared.b64 [%0], %1;" :: "r"(addr), "r"(cnt) : "memory")

#define MB_EXPECT_TX(addr, tx) \
    asm volatile("mbarrier.arrive.expect_tx.shared.b64 _, [%0], %1;" :: "r"(addr), "r"(tx) : "memory")

#define MB_ARRIVE(addr) \
    asm volatile("mbarrier.arrive.shared.b64 _, [%0];" :: "r"(addr) : "memory")

#define MB_WAIT(addr, ph) do {                                                  \
    unsigned _d = 0;                                                            \
    while (!_d) {                                                               \
        asm volatile("{\n\t.reg .pred p;\n\t"                                   \
            "mbarrier.try_wait.parity.acquire.cta.shared::cta.b64 p, [%1], %2, 0x989680;\n\t" \
            "selp.b32 %0, 1, 0, p;\n\t}"                                        \
            : "=r"(_d) : "r"(addr), "r"(ph) : "memory");                        \
    }                                                                           \
} while (0)

#define BULK_G2S(dst, src, bytes, mbar) \
    asm volatile("cp.async.bulk.shared::cta.global.mbarrier::complete_tx::bytes [%0], [%1], %2, [%3];" \
        :: "r"(dst), "l"(src), "r"(bytes), "r"(mbar) : "memory")

// ---------------------------------------------------------------------------
// Kernel 1: segment-parallel frame pipeline (unchanged; ~4.6us).
// ---------------------------------------------------------------------------
#define SEG   256
#define HALO  128
#define EXTN  512
#define ABASE 120
#define ASZ   272

__global__ void __launch_bounds__(256) frame_kernel(const float* __restrict__ f0g) {
    __shared__ float s_f0[EXTN];
    __shared__ float s_a[ASZ];
    __shared__ float s_b[ASZ];
    __shared__ int   s_prev[EXTN];
    __shared__ int   s_next[EXTN];
    __shared__ int   s_wA[8], s_wB[8];
    __shared__ int   s_seed[2];

    const int blk   = blockIdx.x;
    const int b     = blk >> 5;
    const int seg   = blk & 31;
    const int start = seg * SEG;
    const int EB    = start - HALO;
    const int tid   = threadIdx.x;
    const int lane  = tid & 31;
    const int warp  = tid >> 5;
    const unsigned FULL = 0xffffffffu;
    const float* __restrict__ f0row = f0g + (size_t)b * TFv;

    #pragma unroll
    for (int i = tid; i < EXTN; i += 256) {
        int g = EB + i;
        int gc = g < 0 ? 0 : (g > TFv - 1 ? TFv - 1 : g);
        s_f0[i] = f0row[gc];
    }

    if (warp == 0) {
        int found = -1;
        for (int g0 = EB - 1; g0 >= 0 && found < 0; g0 -= 32) {
            int g = g0 - lane;
            bool v = (g >= 0) && (f0row[g] > 0.0f);
            unsigned m = __ballot_sync(FULL, v);
            if (m) found = g0 - (__ffs(m) - 1);
        }
        if (lane == 0) s_seed[0] = found;
    } else if (warp == 1) {
        int found = TFv;
        for (int g0 = EB + EXTN; g0 < TFv && found == TFv; g0 += 32) {
            int g = g0 + lane;
            bool v = (g < TFv) && (f0row[g] > 0.0f);
            unsigned m = __ballot_sync(FULL, v);
            if (m) found = g0 + (__ffs(m) - 1);
        }
        if (lane == 0) s_seed[1] = found;
    }
    __syncthreads();

    const int li0 = 2 * tid;
    const int g0i = EB + li0;

    int run = -1;
    if (s_f0[li0]     > 0.0f) run = g0i;
    s_prev[li0] = run;
    if (s_f0[li0 + 1] > 0.0f) run = g0i + 1;
    s_prev[li0 + 1] = run;
    int v = run;
    #pragma unroll
    for (int off = 1; off < 32; off <<= 1) {
        int u = __shfl_up_sync(FULL, v, off);
        if (lane >= off && u > v) v = u;
    }
    if (lane == 31) s_wA[warp] = v;
    __syncthreads();
    if (warp == 0 && lane < 8) {
        int x = s_wA[lane];
        #pragma unroll
        for (int off = 1; off < 8; off <<= 1) {
            int u = __shfl_up_sync(0xffu, x, off);
            if (lane >= off && u > x) x = u;
        }
        s_wA[lane] = x;
    }
    __syncthreads();
    {
        int wpre = (warp > 0) ? s_wA[warp - 1] : -1;
        int lp = __shfl_up_sync(FULL, v, 1);
        int epre = (lane > 0) ? lp : -1;
        int pre = (wpre > epre) ? wpre : epre;
        int sd = s_seed[0];
        if (sd > pre) pre = sd;
        if (s_prev[li0]     < pre) s_prev[li0]     = pre;
        int pre1 = (s_prev[li0] > pre) ? s_prev[li0] : pre;
        if (s_prev[li0 + 1] < pre1) s_prev[li0 + 1] = pre1;
    }

    int runn = TFv;
    if (s_f0[li0 + 1] > 0.0f) runn = g0i + 1;
    s_next[li0 + 1] = runn;
    if (s_f0[li0]     > 0.0f) runn = g0i;
    s_next[li0] = runn;
    int v2 = runn;
    #pragma unroll
    for (int off = 1; off < 32; off <<= 1) {
        int u = __shfl_down_sync(FULL, v2, off);
        if (lane + off < 32 && u < v2) v2 = u;
    }
    if (lane == 0) s_wB[warp] = v2;
    __syncthreads();
    if (warp == 0 && lane < 8) {
        int x = s_wB[lane];
        #pragma unroll
        for (int off = 1; off < 8; off <<= 1) {
            int u = __shfl_down_sync(0xffu, x, off);
            if (lane + off < 8 && u < x) x = u;
        }
        s_wB[lane] = x;
    }
    __syncthreads();
    {
        int wsuf = (warp < 7) ? s_wB[warp + 1] : TFv;
        int ln = __shfl_down_sync(FULL, v2, 1);
        int esuf = (lane < 31) ? ln : TFv;
        int suf = (wsuf < esuf) ? wsuf : esuf;
        int sd = s_seed[1];
        if (sd < suf) suf = sd;
        if (s_next[li0 + 1] > suf) s_next[li0 + 1] = suf;
        int suf0 = (s_next[li0 + 1] < suf) ? s_next[li0 + 1] : suf;
        if (s_next[li0] > suf0) s_next[li0] = suf0;
    }
    __syncthreads();

    #pragma unroll
    for (int i = tid; i < ASZ; i += 256) {
        int t = EB + ABASE + i;
        if (t < 0 || t >= TFv) continue;
        int li = ABASE + i;
        float f = s_f0[li];
        if (f > 0.0f) {
            s_a[i] = f;
        } else {
            int lo = s_prev[li], hi = s_next[li];
            int lo_t = (lo >= 0)  ? lo : hi;
            int hi_t = (hi < TFv) ? hi : lo;
            float lov = f0row[lo_t];
            float hiv = f0row[hi_t];
            int sp = hi_t - lo_t; if (sp < 1) sp = 1;
            float w = ((float)t - (float)lo_t) / (float)sp;
            w = fminf(fmaxf(w, 0.0f), 1.0f);
            s_a[i] = lov + w * (hiv - lov);
        }
    }
    __syncthreads();

    {
        const float c0 = -2.0f / 21.0f, c1 = 3.0f / 21.0f, c2 = 6.0f / 21.0f, c3 = 7.0f / 21.0f;
        #pragma unroll
        for (int i = 7 + tid; i < 265; i += 256) {
            int t = (start - 8) + i;
            int m1 = t-1 > 0 ? t-1 : 0;
            int m2 = t-2 > 0 ? t-2 : 0;
            int m3 = t-3 > 0 ? t-3 : 0;
            int p1 = t+1 < TFv-1 ? t+1 : TFv-1;
            int p2 = t+2 < TFv-1 ? t+2 : TFv-1;
            int p3 = t+3 < TFv-1 ? t+3 : TFv-1;
            int off = start - 8;
            s_b[i] = c3 * s_a[t - off]
                   + c2 * (s_a[m1 - off] + s_a[p1 - off])
                   + c1 * (s_a[m2 - off] + s_a[p2 - off])
                   + c0 * (s_a[m3 - off] + s_a[p3 - off]);
        }
    }
    __syncthreads();

    if (tid < 128) {
        int j  = (start >> 1) + tid;
        int t0 = 2 * j, t1 = t0 + 1;
        int t0m = t0 - 1 > 0 ? t0 - 1 : 0;
        int t1p = t1 + 1 < TFv - 1 ? t1 + 1 : TFv - 1;
        int off = start - 8;
        float b0 = s_b[t0 - off], b1 = s_b[t1 - off];
        float d0 = fabsf(s_b[t0m - off] - 2.0f * b0 + b1);
        float d1 = fabsf(b0 - 2.0f * b1 + s_b[t1p - off]);
        g_d2pair[b * TF2v + j] = d0 + d1;
        g_f0pair[b * TF2v + j] = s_f0[(t0 - EB)] + s_f0[(t1 - EB)];
    }
}

// ---------------------------------------------------------------------------
// Kernel 2: TMA producer/consumer pipeline + fused tail.
// 288 threads: warps 0-7 consume, thread 256 (warp 8) produces via
// cp.async.bulk into a 4-stage x 16 KB smem ring. Loading is fully decoupled
// from the consumer FFMA/shfl chains -> MLP no longer gated by warp stalls.
// Tables (d2/f0 pairs) live in consumer registers.
// ---------------------------------------------------------------------------
#define RPB    16
#define NSTAGE 4
#define ROW_BYTES (TF2v * 4)          // 16384
#define NTHR_ROW  288

__global__ void __launch_bounds__(NTHR_ROW, 3) row_kernel(const float* __restrict__ attn,
                                                          const float* __restrict__ uv,
                                                          float* __restrict__ out) {
    extern __shared__ float4 s_buf[];             // NSTAGE * 1024 float4 = 64 KB
    __shared__ unsigned long long s_mbar[2 * NSTAGE];  // full[0..3], empty[4..7]
    __shared__ float red[RPB][3][8];
    __shared__ float s_e[Bv];
    __shared__ int   s_last;

    const int blk = blockIdx.x;            // 0 .. 511
    const int b   = blk >> 5;
    const int rg  = blk & 31;
    const int tid = threadIdx.x;
    const int w   = tid >> 5, l = tid & 31;

    const unsigned mb_full  = smem_u32(&s_mbar[0]);
    const unsigned mb_empty = smem_u32(&s_mbar[NSTAGE]);

    if (tid == 0) {
        #pragma unroll
        for (int s = 0; s < NSTAGE; ++s) {
            MB_INIT(mb_full  + 8 * s, 1);   // producer's expect_tx arrival
            MB_INIT(mb_empty + 8 * s, 8);   // one arrival per consumer warp
        }
    }

    // Consumer-side register tables (stream from L2; 256 KB region, resident)
    float4 d[4], f[4];
    if (tid < 256) {
        const float4* __restrict__ d2p = (const float4*)g_d2pair + (size_t)b * (TF2v / 4);
        const float4* __restrict__ f0p = (const float4*)g_f0pair + (size_t)b * (TF2v / 4);
        #pragma unroll
        for (int k = 0; k < 4; ++k) {
            d[k] = d2p[tid + 256 * k];
            f[k] = f0p[tid + 256 * k];
        }
    }
    __syncthreads();    // mbarrier init visible before any TMA / waits

    const char* __restrict__ gbase =
        (const char*)attn + ((size_t)(b * TPv + rg * RPB)) * ROW_BYTES;

    if (tid == 256) {
        // ---- producer ----
        const unsigned buf0 = smem_u32(s_buf);
        for (int r = 0; r < RPB; ++r) {
            int s = r & (NSTAGE - 1);
            if (r >= NSTAGE) {
                unsigned ph = ((r - NSTAGE) >> 2) & 1u;
                MB_WAIT(mb_empty + 8 * s, ph);
            }
            MB_EXPECT_TX(mb_full + 8 * s, ROW_BYTES);
            BULK_G2S(buf0 + (unsigned)s * ROW_BYTES,
                     (const void*)(gbase + (size_t)r * ROW_BYTES),
                     ROW_BYTES, mb_full + 8 * s);
        }
    } else if (tid < 256) {
        // ---- consumers ----
        for (int r = 0; r < RPB; ++r) {
            int s = r & (NSTAGE - 1);
            unsigned ph = (r >> 2) & 1u;
            MB_WAIT(mb_full + 8 * s, ph);
            const float4* __restrict__ buf = s_buf + (s << 10);
            float sa = 0.f, sc = 0.f, sm = 0.f;
            #pragma unroll
            for (int k = 0; k < 4; ++k) {
                float4 a = buf[tid + (k << 8)];
                sa += (a.x + a.y) + (a.z + a.w);
                sc += a.x * d[k].x + a.y * d[k].y + a.z * d[k].z + a.w * d[k].w;
                sm += a.x * f[k].x + a.y * f[k].y + a.z * f[k].z + a.w * f[k].w;
            }
            #pragma unroll
            for (int o = 16; o > 0; o >>= 1) {
                sa += __shfl_down_sync(0xffffffffu, sa, o);
                sc += __shfl_down_sync(0xffffffffu, sc, o);
                sm += __shfl_down_sync(0xffffffffu, sm, o);
            }
            // shfl chain synchronizes the warp: all lanes' LDS reads of buf[s]
            // retired before lane 0 releases the stage.
            if (l == 0) {
                red[r][0][w] = sa; red[r][1][w] = sc; red[r][2][w] = sm;
                MB_ARRIVE(mb_empty + 8 * s);
            }
        }
    }
    __syncthreads();

    if (tid < RPB) {
        float sa = 0.0f, sc = 0.0f, sm = 0.0f;
        #pragma unroll
        for (int i = 0; i < 8; ++i) {
            sa += red[tid][0][i]; sc += red[tid][1][i]; sm += red[tid][2][i];
        }
        float denom = fmaxf(2.0f * sa, 1.0f);
        float inv   = 1.0f / (denom + EPSv);
        int bid = b * TPv + rg * RPB + tid;
        out[bid]            = sc * inv;   // curv_phn
        out[Bv * TPv + bid] = sm * inv;   // mean_phn
    }

    // ---- last-block epilogue ----
    __threadfence();
    __syncthreads();
    if (tid == 0) {
        unsigned old = atomicAdd(&g_ctr, 1u);
        s_last = (old == (unsigned)(gridDim.x - 1)) ? 1 : 0;
    }
    __syncthreads();
    if (!s_last) return;
    if (tid == 0) g_ctr = 0;
    __threadfence();

    const float OODM =  21.688259064691245f;   // 12*log2(350/100)
    const float OODC = -71.589411415945055f;   // 12*log2(1.6/100)

    if (w < 8) {
        #pragma unroll
        for (int pass = 0; pass < 2; ++pass) {
            int bb = w + 8 * pass;
            float dm = 0.0f, vm = 0.0f, dc = 0.0f, vc = 0.0f;
            #pragma unroll
            for (int k = 0; k < TPv / 32; ++k) {
                int p = l + 32 * k;
                float u  = uv[bb * TPv + p];
                float cv = out[bb * TPv + p];
                float mv = out[Bv * TPv + bb * TPv + p];

                float pvm = mv * u;
                float vmi = (pvm != 0.0f) ? 1.0f : 0.0f;
                float semim = 12.0f * log2f(fmaxf(pvm, 1e-6f) * 0.01f);
                dm += fmaxf(OODM - semim, 0.0f) * vmi;
                vm += vmi;

                float pvc = cv * u;
                float vci = (pvc != 0.0f) ? 1.0f : 0.0f;
                float semic = 12.0f * log2f(fmaxf(pvc, 1e-6f) * 0.01f);
                dc += fmaxf(OODC - semic, 0.0f) * vci;
                vc += vci;
            }
            #pragma unroll
            for (int o = 16; o > 0; o >>= 1) {
                dm += __shfl_down_sync(0xffffffffu, dm, o);
                vm += __shfl_down_sync(0xffffffffu, vm, o);
                dc += __shfl_down_sync(0xffffffffu, dc, o);
                vc += __shfl_down_sync(0xffffffffu, vc, o);
            }
            if (l == 0) s_e[bb] = dm / fmaxf(vm, 1.0f) + dc / fmaxf(vc, 1.0f);
        }
    }
    __syncthreads();

    if (tid == 0) {
        float e[Bv];
        float m = 0.0f;
        #pragma unroll
        for (int i = 0; i < Bv; ++i) { e[i] = s_e[i]; m += e[i]; }
        m /= (float)Bv;
        float var = 0.0f;
        #pragma unroll
        for (int i = 0; i < Bv; ++i) { float dd = e[i] - m; var += dd * dd; }
        var /= (float)Bv;
        float sd = fmaxf(sqrtf(var), 1e-6f);
        float x[Bv], mx = -1e30f;
        #pragma unroll
        for (int i = 0; i < Bv; ++i) { x[i] = -(e[i] - m) / sd; mx = fmaxf(mx, x[i]); }
        float s = 0.0f;
        #pragma unroll
        for (int i = 0; i < Bv; ++i) { x[i] = expf(x[i] - mx); s += x[i]; }
        float s2 = 0.0f;
        #pragma unroll
        for (int i = 0; i < Bv; ++i) { float wv = x[i] / s; x[i] = wv; s2 += wv * wv; }
        #pragma unroll
        for (int i = 0; i < Bv; ++i) out[2 * Bv * TPv + i] = (float)Bv * x[i];
        out[2 * Bv * TPv + Bv] = 1.0f / s2;
    }
}

// ---------------------------------------------------------------------------

extern "C" void kernel_launch(void* const* d_in, const int* in_sizes, int n_in,
                              void* d_out, int out_size) {
    const float* f0   = (const float*)d_in[0];   // [B, TF]
    const float* attn = (const float*)d_in[1];   // [B, TP, TF2]
    const float* uv   = (const float*)d_in[2];   // [B, TP]
    float* out = (float*)d_out;                  // curv | mean | B*wts | ess

    const int dyn = NSTAGE * ROW_BYTES;          // 64 KB staging ring
    cudaFuncSetAttribute(row_kernel, cudaFuncAttributeMaxDynamicSharedMemorySize, dyn);

    frame_kernel<<<Bv * 32, 256>>>(f0);
    row_kernel<<<(Bv * TPv) / RPB, NTHR_ROW, dyn>>>(attn, uv, out);
}

// round 15
// speedup vs baseline: 1.1024x; 1.0960x over previous
#include <cuda_runtime.h>
#include <math.h>

#define TFv  8192
#define TF2v 4096
#define TPv  512
#define Bv   16
#define EPSv 1e-8f

// Scratch (no allocations allowed -> device globals; zero-initialized)
__device__ float    g_d2pair[Bv * TF2v];
__device__ float    g_f0pair[Bv * TF2v];
__device__ unsigned g_bctr[Bv];   // per-batch frame-segment arrival counters
__device__ unsigned g_ctr = 0;    // last-block epilogue counter (self-resetting)

// ---------------------------------------------------------------------------
// ONE fused persistent kernel. Grid = 512 blocks (16 batches x 32 segments),
// 256 threads. All 512 blocks are co-resident (<=64 regs, ~41 KB smem ->
// >=4 CTAs/SM), so the per-batch spin-wait is deadlock-free: every block runs
// its frame phase BEFORE any wait.
//   Phase 1: frame segment (interp -> SG -> |d2| -> pair-fold) for (b, seg)
//   Phase 2: release-arrive on g_bctr[b]; spin until all 32 segments of b land
//   Phase 3: warp-per-row triple-dot over 16 attn rows (2 rows per warp)
//   Phase 4: last block computes energies + softmax + ESS, resets counters
// ---------------------------------------------------------------------------
#define SEG   256
#define HALO  128
#define EXTN  512
#define ABASE 120
#define ASZ   272
#define RPB   16

__global__ void __launch_bounds__(256, 4) mega_kernel(const float* __restrict__ f0g,
                                                      const float* __restrict__ attn,
                                                      const float* __restrict__ uv,
                                                      float* __restrict__ out) {
    // frame-phase shared
    __shared__ float s_f0[EXTN];
    __shared__ float s_a[ASZ];
    __shared__ float s_b[ASZ];
    __shared__ int   s_prev[EXTN];
    __shared__ int   s_next[EXTN];
    __shared__ int   s_wA[8], s_wB[8];
    __shared__ int   s_seed[2];
    // row-phase shared
    __shared__ float4 s_d[TF2v / 4];     // 16 KB
    __shared__ float4 s_f[TF2v / 4];     // 16 KB
    // tail shared
    __shared__ float s_e[Bv];
    __shared__ int   s_last;

    const int blk   = blockIdx.x;        // 0..511
    const int b     = blk >> 5;          // batch (frame segment AND row group)
    const int seg   = blk & 31;
    const int start = seg * SEG;
    const int EB    = start - HALO;
    const int tid   = threadIdx.x;
    const int lane  = tid & 31;
    const int warp  = tid >> 5;          // 8 warps
    const unsigned FULL = 0xffffffffu;
    const float* __restrict__ f0row = f0g + (size_t)b * TFv;

    // ======================= Phase 1: frame segment =======================
    #pragma unroll
    for (int i = tid; i < EXTN; i += 256) {
        int g = EB + i;
        int gc = g < 0 ? 0 : (g > TFv - 1 ? TFv - 1 : g);
        s_f0[i] = f0row[gc];
    }

    if (warp == 0) {
        int found = -1;
        for (int g0 = EB - 1; g0 >= 0 && found < 0; g0 -= 32) {
            int g = g0 - lane;
            bool v = (g >= 0) && (f0row[g] > 0.0f);
            unsigned m = __ballot_sync(FULL, v);
            if (m) found = g0 - (__ffs(m) - 1);
        }
        if (lane == 0) s_seed[0] = found;
    } else if (warp == 1) {
        int found = TFv;
        for (int g0 = EB + EXTN; g0 < TFv && found == TFv; g0 += 32) {
            int g = g0 + lane;
            bool v = (g < TFv) && (f0row[g] > 0.0f);
            unsigned m = __ballot_sync(FULL, v);
            if (m) found = g0 + (__ffs(m) - 1);
        }
        if (lane == 0) s_seed[1] = found;
    }
    __syncthreads();

    const int li0 = 2 * tid;
    const int g0i = EB + li0;

    // forward cummax of (voiced ? global_idx : -1)
    int run = -1;
    if (s_f0[li0]     > 0.0f) run = g0i;
    s_prev[li0] = run;
    if (s_f0[li0 + 1] > 0.0f) run = g0i + 1;
    s_prev[li0 + 1] = run;
    int v = run;
    #pragma unroll
    for (int off = 1; off < 32; off <<= 1) {
        int u = __shfl_up_sync(FULL, v, off);
        if (lane >= off && u > v) v = u;
    }
    if (lane == 31) s_wA[warp] = v;
    __syncthreads();
    if (warp == 0 && lane < 8) {
        int x = s_wA[lane];
        #pragma unroll
        for (int off = 1; off < 8; off <<= 1) {
            int u = __shfl_up_sync(0xffu, x, off);
            if (lane >= off && u > x) x = u;
        }
        s_wA[lane] = x;
    }
    __syncthreads();
    {
        int wpre = (warp > 0) ? s_wA[warp - 1] : -1;
        int lp = __shfl_up_sync(FULL, v, 1);
        int epre = (lane > 0) ? lp : -1;
        int pre = (wpre > epre) ? wpre : epre;
        int sd = s_seed[0];
        if (sd > pre) pre = sd;
        if (s_prev[li0]     < pre) s_prev[li0]     = pre;
        int pre1 = (s_prev[li0] > pre) ? s_prev[li0] : pre;
        if (s_prev[li0 + 1] < pre1) s_prev[li0 + 1] = pre1;
    }

    // backward cummin of (voiced ? global_idx : TFv)
    int runn = TFv;
    if (s_f0[li0 + 1] > 0.0f) runn = g0i + 1;
    s_next[li0 + 1] = runn;
    if (s_f0[li0]     > 0.0f) runn = g0i;
    s_next[li0] = runn;
    int v2 = runn;
    #pragma unroll
    for (int off = 1; off < 32; off <<= 1) {
        int u = __shfl_down_sync(FULL, v2, off);
        if (lane + off < 32 && u < v2) v2 = u;
    }
    if (lane == 0) s_wB[warp] = v2;
    __syncthreads();
    if (warp == 0 && lane < 8) {
        int x = s_wB[lane];
        #pragma unroll
        for (int off = 1; off < 8; off <<= 1) {
            int u = __shfl_down_sync(0xffu, x, off);
            if (lane + off < 8 && u < x) x = u;
        }
        s_wB[lane] = x;
    }
    __syncthreads();
    {
        int wsuf = (warp < 7) ? s_wB[warp + 1] : TFv;
        int ln = __shfl_down_sync(FULL, v2, 1);
        int esuf = (lane < 31) ? ln : TFv;
        int suf = (wsuf < esuf) ? wsuf : esuf;
        int sd = s_seed[1];
        if (sd < suf) suf = sd;
        if (s_next[li0 + 1] > suf) s_next[li0 + 1] = suf;
        int suf0 = (s_next[li0 + 1] < suf) ? s_next[li0 + 1] : suf;
        if (s_next[li0] > suf0) s_next[li0] = suf0;
    }
    __syncthreads();

    // interp unvoiced for t in [start-8, start+264) ∩ [0, TFv)
    #pragma unroll
    for (int i = tid; i < ASZ; i += 256) {
        int t = EB + ABASE + i;
        if (t < 0 || t >= TFv) continue;
        int li = ABASE + i;
        float f = s_f0[li];
        if (f > 0.0f) {
            s_a[i] = f;
        } else {
            int lo = s_prev[li], hi = s_next[li];
            int lo_t = (lo >= 0)  ? lo : hi;
            int hi_t = (hi < TFv) ? hi : lo;
            float lov = f0row[lo_t];
            float hiv = f0row[hi_t];
            int sp = hi_t - lo_t; if (sp < 1) sp = 1;
            float w = ((float)t - (float)lo_t) / (float)sp;
            w = fminf(fmaxf(w, 0.0f), 1.0f);
            s_a[i] = lov + w * (hiv - lov);
        }
    }
    __syncthreads();

    // SG smooth
    {
        const float c0 = -2.0f / 21.0f, c1 = 3.0f / 21.0f, c2 = 6.0f / 21.0f, c3 = 7.0f / 21.0f;
        #pragma unroll
        for (int i = 7 + tid; i < 265; i += 256) {
            int t = (start - 8) + i;
            int m1 = t-1 > 0 ? t-1 : 0;
            int m2 = t-2 > 0 ? t-2 : 0;
            int m3 = t-3 > 0 ? t-3 : 0;
            int p1 = t+1 < TFv-1 ? t+1 : TFv-1;
            int p2 = t+2 < TFv-1 ? t+2 : TFv-1;
            int p3 = t+3 < TFv-1 ? t+3 : TFv-1;
            int off = start - 8;
            s_b[i] = c3 * s_a[t - off]
                   + c2 * (s_a[m1 - off] + s_a[p1 - off])
                   + c1 * (s_a[m2 - off] + s_a[p2 - off])
                   + c0 * (s_a[m3 - off] + s_a[p3 - off]);
        }
    }
    __syncthreads();

    // |d2| + pair-fold
    if (tid < 128) {
        int j  = (start >> 1) + tid;
        int t0 = 2 * j, t1 = t0 + 1;
        int t0m = t0 - 1 > 0 ? t0 - 1 : 0;
        int t1p = t1 + 1 < TFv - 1 ? t1 + 1 : TFv - 1;
        int off = start - 8;
        float b0 = s_b[t0 - off], b1 = s_b[t1 - off];
        float d0 = fabsf(s_b[t0m - off] - 2.0f * b0 + b1);
        float d1 = fabsf(b0 - 2.0f * b1 + s_b[t1p - off]);
        g_d2pair[b * TF2v + j] = d0 + d1;
        g_f0pair[b * TF2v + j] = s_f0[(t0 - EB)] + s_f0[(t1 - EB)];
    }

    // ============ Phase 2: release-arrive + wait for batch tables ============
    __threadfence();          // release our g_d2pair/g_f0pair writes
    __syncthreads();          // whole block's segment is written
    if (tid == 0) {
        atomicAdd(&g_bctr[b], 1u);
        while (atomicAdd(&g_bctr[b], 0u) < 32u) __nanosleep(64);
    }
    __syncthreads();
    __threadfence();          // acquire: all 32 segments' table writes visible

    // load batch tables into smem
    {
        const float4* __restrict__ d2p = (const float4*)g_d2pair + (size_t)b * (TF2v / 4);
        const float4* __restrict__ f0p = (const float4*)g_f0pair + (size_t)b * (TF2v / 4);
        #pragma unroll
        for (int i = tid; i < TF2v / 4; i += 256) {
            s_d[i] = d2p[i];
            s_f[i] = f0p[i];
        }
    }
    __syncthreads();

    // ================= Phase 3: warp-per-row triple dots =================
    // Block owns rows [b*TPv + seg*RPB, +16); warp w handles rows 2w, 2w+1.
    {
        const float4* __restrict__ base =
            (const float4*)attn + ((size_t)(b * TPv + seg * RPB)) * (TF2v / 4);
        #pragma unroll
        for (int rr = 0; rr < 2; ++rr) {
            const int r = 2 * warp + rr;
            const float4* __restrict__ r4 = base + (size_t)r * (TF2v / 4);
            float sa = 0.f, sc = 0.f, sm = 0.f;
            #pragma unroll
            for (int k8 = 0; k8 < 4; ++k8) {
                float4 a[8];
                #pragma unroll
                for (int u = 0; u < 8; ++u)
                    a[u] = __ldcs(&r4[lane + 32 * (8 * k8 + u)]);
                #pragma unroll
                for (int u = 0; u < 8; ++u) {
                    int idx = lane + 32 * (8 * k8 + u);
                    float4 d = s_d[idx];
                    float4 f = s_f[idx];
                    sa += (a[u].x + a[u].y) + (a[u].z + a[u].w);
                    sc += a[u].x * d.x + a[u].y * d.y + a[u].z * d.z + a[u].w * d.w;
                    sm += a[u].x * f.x + a[u].y * f.y + a[u].z * f.z + a[u].w * f.w;
                }
            }
            #pragma unroll
            for (int o = 16; o > 0; o >>= 1) {
                sa += __shfl_down_sync(FULL, sa, o);
                sc += __shfl_down_sync(FULL, sc, o);
                sm += __shfl_down_sync(FULL, sm, o);
            }
            if (lane == 0) {
                float denom = fmaxf(2.0f * sa, 1.0f);
                float inv   = 1.0f / (denom + EPSv);
                int bid = b * TPv + seg * RPB + r;
                out[bid]            = sc * inv;   // curv_phn
                out[Bv * TPv + bid] = sm * inv;   // mean_phn
            }
        }
    }

    // ===================== Phase 4: last-block epilogue =====================
    __threadfence();
    __syncthreads();
    if (tid == 0) {
        unsigned old = atomicAdd(&g_ctr, 1u);
        s_last = (old == (unsigned)(gridDim.x - 1)) ? 1 : 0;
    }
    __syncthreads();
    if (!s_last) return;
    if (tid == 0) {
        g_ctr = 0;
        #pragma unroll
        for (int i = 0; i < Bv; ++i) g_bctr[i] = 0;   // reset for next replay
    }
    __threadfence();   // acquire: all blocks' out[] writes visible

    const float OODM =  21.688259064691245f;   // 12*log2(350/100)
    const float OODC = -71.589411415945055f;   // 12*log2(1.6/100)

    #pragma unroll
    for (int pass = 0; pass < 2; ++pass) {
        int bb = warp + 8 * pass;
        float dm = 0.0f, vm = 0.0f, dc = 0.0f, vc = 0.0f;
        #pragma unroll
        for (int k = 0; k < TPv / 32; ++k) {
            int p = lane + 32 * k;
            float u  = uv[bb * TPv + p];
            float cv = out[bb * TPv + p];
            float mv = out[Bv * TPv + bb * TPv + p];

            float pvm = mv * u;
            float vmi = (pvm != 0.0f) ? 1.0f : 0.0f;
            float semim = 12.0f * log2f(fmaxf(pvm, 1e-6f) * 0.01f);
            dm += fmaxf(OODM - semim, 0.0f) * vmi;
            vm += vmi;

            float pvc = cv * u;
            float vci = (pvc != 0.0f) ? 1.0f : 0.0f;
            float semic = 12.0f * log2f(fmaxf(pvc, 1e-6f) * 0.01f);
            dc += fmaxf(OODC - semic, 0.0f) * vci;
            vc += vci;
        }
        #pragma unroll
        for (int o = 16; o > 0; o >>= 1) {
            dm += __shfl_down_sync(FULL, dm, o);
            vm += __shfl_down_sync(FULL, vm, o);
            dc += __shfl_down_sync(FULL, dc, o);
            vc += __shfl_down_sync(FULL, vc, o);
        }
        if (lane == 0) s_e[bb] = dm / fmaxf(vm, 1.0f) + dc / fmaxf(vc, 1.0f);
    }
    __syncthreads();

    if (tid == 0) {
        float e[Bv];
        float m = 0.0f;
        #pragma unroll
        for (int i = 0; i < Bv; ++i) { e[i] = s_e[i]; m += e[i]; }
        m /= (float)Bv;
        float var = 0.0f;
        #pragma unroll
        for (int i = 0; i < Bv; ++i) { float dd = e[i] - m; var += dd * dd; }
        var /= (float)Bv;
        float sd = fmaxf(sqrtf(var), 1e-6f);
        float x[Bv], mx = -1e30f;
        #pragma unroll
        for (int i = 0; i < Bv; ++i) { x[i] = -(e[i] - m) / sd; mx = fmaxf(mx, x[i]); }
        float s = 0.0f;
        #pragma unroll
        for (int i = 0; i < Bv; ++i) { x[i] = expf(x[i] - mx); s += x[i]; }
        float s2 = 0.0f;
        #pragma unroll
        for (int i = 0; i < Bv; ++i) { float wv = x[i] / s; x[i] = wv; s2 += wv * wv; }
        #pragma unroll
        for (int i = 0; i < Bv; ++i) out[2 * Bv * TPv + i] = (float)Bv * x[i];
        out[2 * Bv * TPv + Bv] = 1.0f / s2;
    }
}

// ---------------------------------------------------------------------------

extern "C" void kernel_launch(void* const* d_in, const int* in_sizes, int n_in,
                              void* d_out, int out_size) {
    const float* f0   = (const float*)d_in[0];   // [B, TF]
    const float* attn = (const float*)d_in[1];   // [B, TP, TF2]
    const float* uv   = (const float*)d_in[2];   // [B, TP]
    float* out = (float*)d_out;                  // curv | mean | B*wts | ess

    mega_kernel<<<Bv * 32, 256>>>(f0, attn, uv, out);
}

// round 17
// speedup vs baseline: 1.1856x; 1.0755x over previous
#include <cuda_runtime.h>
#include <math.h>

#define TFv  8192
#define TF2v 4096
#define TPv  512
#define Bv   16
#define EPSv 1e-8f

// Scratch (no allocations allowed -> device globals; zero-initialized)
__device__ float    g_d2pair[Bv * TF2v];
__device__ float    g_f0pair[Bv * TF2v];
__device__ unsigned g_bctr[Bv];   // per-batch frame-segment arrival counters
__device__ unsigned g_ctr = 0;    // last-block epilogue counter (self-resetting)

// ---------------------------------------------------------------------------
// ONE fused persistent kernel. Grid = 512 blocks (16 batches x 32 segments),
// 256 threads; all co-resident (~11 KB smem, ~60 regs -> 4 CTAs/SM) so the
// per-batch spin-wait is deadlock-free (every block's frame phase precedes
// any wait).
//   Phase 1: frame segment (interp -> SG -> |d2| -> pair-fold) for (b, seg)
//   Phase 2: release-arrive on g_bctr[b]; spin until all 32 segments of b land
//   Phase 3: R9-style block-wide triple-dot over 16 attn rows, tables in regs
//   Phase 4: last block computes energies + softmax + ESS, resets counters
// ---------------------------------------------------------------------------
#define SEG   256
#define HALO  128
#define EXTN  512
#define ABASE 120
#define ASZ   272
#define RPB   16

__global__ void __launch_bounds__(256, 4) mega_kernel(const float* __restrict__ f0g,
                                                      const float* __restrict__ attn,
                                                      const float* __restrict__ uv,
                                                      float* __restrict__ out) {
    // frame-phase shared
    __shared__ float s_f0[EXTN];
    __shared__ float s_a[ASZ];
    __shared__ float s_b[ASZ];
    __shared__ int   s_prev[EXTN];
    __shared__ int   s_next[EXTN];
    __shared__ int   s_wA[8], s_wB[8];
    __shared__ int   s_seed[2];
    // row-phase shared
    __shared__ float red[RPB][3][8];
    // tail shared
    __shared__ float s_e[Bv];
    __shared__ int   s_last;

    const int blk   = blockIdx.x;        // 0..511
    const int b     = blk >> 5;          // batch (frame segment AND row group)
    const int seg   = blk & 31;
    const int start = seg * SEG;
    const int EB    = start - HALO;
    const int tid   = threadIdx.x;
    const int lane  = tid & 31;
    const int warp  = tid >> 5;          // 8 warps
    const unsigned FULL = 0xffffffffu;
    const float* __restrict__ f0row = f0g + (size_t)b * TFv;

    // ======================= Phase 1: frame segment =======================
    #pragma unroll
    for (int i = tid; i < EXTN; i += 256) {
        int g = EB + i;
        int gc = g < 0 ? 0 : (g > TFv - 1 ? TFv - 1 : g);
        s_f0[i] = f0row[gc];
    }

    if (warp == 0) {
        int found = -1;
        for (int g0 = EB - 1; g0 >= 0 && found < 0; g0 -= 32) {
            int g = g0 - lane;
            bool v = (g >= 0) && (f0row[g] > 0.0f);
            unsigned m = __ballot_sync(FULL, v);
            if (m) found = g0 - (__ffs(m) - 1);
        }
        if (lane == 0) s_seed[0] = found;
    } else if (warp == 1) {
        int found = TFv;
        for (int g0 = EB + EXTN; g0 < TFv && found == TFv; g0 += 32) {
            int g = g0 + lane;
            bool v = (g < TFv) && (f0row[g] > 0.0f);
            unsigned m = __ballot_sync(FULL, v);
            if (m) found = g0 + (__ffs(m) - 1);
        }
        if (lane == 0) s_seed[1] = found;
    }
    __syncthreads();

    const int li0 = 2 * tid;
    const int g0i = EB + li0;

    // forward cummax of (voiced ? global_idx : -1)
    int run = -1;
    if (s_f0[li0]     > 0.0f) run = g0i;
    s_prev[li0] = run;
    if (s_f0[li0 + 1] > 0.0f) run = g0i + 1;
    s_prev[li0 + 1] = run;
    int v = run;
    #pragma unroll
    for (int off = 1; off < 32; off <<= 1) {
        int u = __shfl_up_sync(FULL, v, off);
        if (lane >= off && u > v) v = u;
    }
    if (lane == 31) s_wA[warp] = v;
    __syncthreads();
    if (warp == 0 && lane < 8) {
        int x = s_wA[lane];
        #pragma unroll
        for (int off = 1; off < 8; off <<= 1) {
            int u = __shfl_up_sync(0xffu, x, off);
            if (lane >= off && u > x) x = u;
        }
        s_wA[lane] = x;
    }
    __syncthreads();
    {
        int wpre = (warp > 0) ? s_wA[warp - 1] : -1;
        int lp = __shfl_up_sync(FULL, v, 1);
        int epre = (lane > 0) ? lp : -1;
        int pre = (wpre > epre) ? wpre : epre;
        int sd = s_seed[0];
        if (sd > pre) pre = sd;
        if (s_prev[li0]     < pre) s_prev[li0]     = pre;
        int pre1 = (s_prev[li0] > pre) ? s_prev[li0] : pre;
        if (s_prev[li0 + 1] < pre1) s_prev[li0 + 1] = pre1;
    }

    // backward cummin of (voiced ? global_idx : TFv)
    int runn = TFv;
    if (s_f0[li0 + 1] > 0.0f) runn = g0i + 1;
    s_next[li0 + 1] = runn;
    if (s_f0[li0]     > 0.0f) runn = g0i;
    s_next[li0] = runn;
    int v2 = runn;
    #pragma unroll
    for (int off = 1; off < 32; off <<= 1) {
        int u = __shfl_down_sync(FULL, v2, off);
        if (lane + off < 32 && u < v2) v2 = u;
    }
    if (lane == 0) s_wB[warp] = v2;
    __syncthreads();
    if (warp == 0 && lane < 8) {
        int x = s_wB[lane];
        #pragma unroll
        for (int off = 1; off < 8; off <<= 1) {
            int u = __shfl_down_sync(0xffu, x, off);
            if (lane + off < 8 && u < x) x = u;
        }
        s_wB[lane] = x;
    }
    __syncthreads();
    {
        int wsuf = (warp < 7) ? s_wB[warp + 1] : TFv;
        int ln = __shfl_down_sync(FULL, v2, 1);
        int esuf = (lane < 31) ? ln : TFv;
        int suf = (wsuf < esuf) ? wsuf : esuf;
        int sd = s_seed[1];
        if (sd < suf) suf = sd;
        if (s_next[li0 + 1] > suf) s_next[li0 + 1] = suf;
        int suf0 = (s_next[li0 + 1] < suf) ? s_next[li0 + 1] : suf;
        if (s_next[li0] > suf0) s_next[li0] = suf0;
    }
    __syncthreads();

    // interp unvoiced for t in [start-8, start+264) ∩ [0, TFv)
    #pragma unroll
    for (int i = tid; i < ASZ; i += 256) {
        int t = EB + ABASE + i;
        if (t < 0 || t >= TFv) continue;
        int li = ABASE + i;
        float f = s_f0[li];
        if (f > 0.0f) {
            s_a[i] = f;
        } else {
            int lo = s_prev[li], hi = s_next[li];
            int lo_t = (lo >= 0)  ? lo : hi;
            int hi_t = (hi < TFv) ? hi : lo;
            float lov = f0row[lo_t];
            float hiv = f0row[hi_t];
            int sp = hi_t - lo_t; if (sp < 1) sp = 1;
            float w = ((float)t - (float)lo_t) / (float)sp;
            w = fminf(fmaxf(w, 0.0f), 1.0f);
            s_a[i] = lov + w * (hiv - lov);
        }
    }
    __syncthreads();

    // SG smooth
    {
        const float c0 = -2.0f / 21.0f, c1 = 3.0f / 21.0f, c2 = 6.0f / 21.0f, c3 = 7.0f / 21.0f;
        #pragma unroll
        for (int i = 7 + tid; i < 265; i += 256) {
            int t = (start - 8) + i;
            int m1 = t-1 > 0 ? t-1 : 0;
            int m2 = t-2 > 0 ? t-2 : 0;
            int m3 = t-3 > 0 ? t-3 : 0;
            int p1 = t+1 < TFv-1 ? t+1 : TFv-1;
            int p2 = t+2 < TFv-1 ? t+2 : TFv-1;
            int p3 = t+3 < TFv-1 ? t+3 : TFv-1;
            int off = start - 8;
            s_b[i] = c3 * s_a[t - off]
                   + c2 * (s_a[m1 - off] + s_a[p1 - off])
                   + c1 * (s_a[m2 - off] + s_a[p2 - off])
                   + c0 * (s_a[m3 - off] + s_a[p3 - off]);
        }
    }
    __syncthreads();

    // |d2| + pair-fold
    if (tid < 128) {
        int j  = (start >> 1) + tid;
        int t0 = 2 * j, t1 = t0 + 1;
        int t0m = t0 - 1 > 0 ? t0 - 1 : 0;
        int t1p = t1 + 1 < TFv - 1 ? t1 + 1 : TFv - 1;
        int off = start - 8;
        float b0 = s_b[t0 - off], b1 = s_b[t1 - off];
        float d0 = fabsf(s_b[t0m - off] - 2.0f * b0 + b1);
        float d1 = fabsf(b0 - 2.0f * b1 + s_b[t1p - off]);
        g_d2pair[b * TF2v + j] = d0 + d1;
        g_f0pair[b * TF2v + j] = s_f0[(t0 - EB)] + s_f0[(t1 - EB)];
    }

    // ============ Phase 2: release-arrive + wait for batch tables ============
    __threadfence();          // release our g_d2pair/g_f0pair writes
    __syncthreads();          // whole block's segment is written
    if (tid == 0) {
        atomicAdd(&g_bctr[b], 1u);
        while (atomicAdd(&g_bctr[b], 0u) < 32u) __nanosleep(64);
    }
    __syncthreads();
    __threadfence();          // acquire: all 32 segments' table writes visible

    // =========== Phase 3: R9-style block-wide triple dots ===========
    // Tables in registers; 16 rows, 2 per iteration, interleaved load/FMA.
    {
        const float4* __restrict__ d2p = (const float4*)g_d2pair + (size_t)b * (TF2v / 4);
        const float4* __restrict__ f0p = (const float4*)g_f0pair + (size_t)b * (TF2v / 4);
        float4 d[4], f[4];
        #pragma unroll
        for (int k = 0; k < 4; ++k) {
            d[k] = d2p[tid + 256 * k];
            f[k] = f0p[tid + 256 * k];
        }

        const float4* __restrict__ base =
            (const float4*)attn + ((size_t)(b * TPv + seg * RPB)) * (TF2v / 4);

        for (int rp = 0; rp < RPB; rp += 2) {
            const float4* __restrict__ row0 = base + (size_t)rp * (TF2v / 4);
            const float4* __restrict__ row1 = row0 + (TF2v / 4);
            float sa0 = 0.f, sc0 = 0.f, sm0 = 0.f;
            float sa1 = 0.f, sc1 = 0.f, sm1 = 0.f;
            #pragma unroll
            for (int k = 0; k < 4; ++k) {
                int idx = tid + 256 * k;
                float4 a0 = __ldcs(&row0[idx]);
                float4 a1 = __ldcs(&row1[idx]);
                sa0 += (a0.x + a0.y) + (a0.z + a0.w);
                sc0 += a0.x * d[k].x + a0.y * d[k].y + a0.z * d[k].z + a0.w * d[k].w;
                sm0 += a0.x * f[k].x + a0.y * f[k].y + a0.z * f[k].z + a0.w * f[k].w;
                sa1 += (a1.x + a1.y) + (a1.z + a1.w);
                sc1 += a1.x * d[k].x + a1.y * d[k].y + a1.z * d[k].z + a1.w * d[k].w;
                sm1 += a1.x * f[k].x + a1.y * f[k].y + a1.z * f[k].z + a1.w * f[k].w;
            }
            #pragma unroll
            for (int o = 16; o > 0; o >>= 1) {
                sa0 += __shfl_down_sync(FULL, sa0, o);
                sc0 += __shfl_down_sync(FULL, sc0, o);
                sm0 += __shfl_down_sync(FULL, sm0, o);
                sa1 += __shfl_down_sync(FULL, sa1, o);
                sc1 += __shfl_down_sync(FULL, sc1, o);
                sm1 += __shfl_down_sync(FULL, sm1, o);
            }
            if (lane == 0) {
                red[rp][0][warp]     = sa0; red[rp][1][warp]     = sc0; red[rp][2][warp]     = sm0;
                red[rp + 1][0][warp] = sa1; red[rp + 1][1][warp] = sc1; red[rp + 1][2][warp] = sm1;
            }
        }
    }
    __syncthreads();

    if (tid < RPB) {
        float sa = 0.0f, sc = 0.0f, sm = 0.0f;
        #pragma unroll
        for (int i = 0; i < 8; ++i) {
            sa += red[tid][0][i]; sc += red[tid][1][i]; sm += red[tid][2][i];
        }
        float denom = fmaxf(2.0f * sa, 1.0f);
        float inv   = 1.0f / (denom + EPSv);
        int bid = b * TPv + seg * RPB + tid;
        out[bid]            = sc * inv;   // curv_phn
        out[Bv * TPv + bid] = sm * inv;   // mean_phn
    }

    // ===================== Phase 4: last-block epilogue =====================
    __threadfence();
    __syncthreads();
    if (tid == 0) {
        unsigned old = atomicAdd(&g_ctr, 1u);
        s_last = (old == (unsigned)(gridDim.x - 1)) ? 1 : 0;
    }
    __syncthreads();
    if (!s_last) return;
    if (tid == 0) {
        g_ctr = 0;
        #pragma unroll
        for (int i = 0; i < Bv; ++i) g_bctr[i] = 0;   // reset for next replay
    }
    __threadfence();   // acquire: all blocks' out[] writes visible

    const float OODM =  21.688259064691245f;   // 12*log2(350/100)
    const float OODC = -71.589411415945055f;   // 12*log2(1.6/100)

    #pragma unroll
    for (int pass = 0; pass < 2; ++pass) {
        int bb = warp + 8 * pass;
        float dm = 0.0f, vm = 0.0f, dc = 0.0f, vc = 0.0f;
        #pragma unroll
        for (int k = 0; k < TPv / 32; ++k) {
            int p = lane + 32 * k;
            float u  = uv[bb * TPv + p];
            float cv = out[bb * TPv + p];
            float mv = out[Bv * TPv + bb * TPv + p];

            float pvm = mv * u;
            float vmi = (pvm != 0.0f) ? 1.0f : 0.0f;
            float semim = 12.0f * log2f(fmaxf(pvm, 1e-6f) * 0.01f);
            dm += fmaxf(OODM - semim, 0.0f) * vmi;
            vm += vmi;

            float pvc = cv * u;
            float vci = (pvc != 0.0f) ? 1.0f : 0.0f;
            float semic = 12.0f * log2f(fmaxf(pvc, 1e-6f) * 0.01f);
            dc += fmaxf(OODC - semic, 0.0f) * vci;
            vc += vci;
        }
        #pragma unroll
        for (int o = 16; o > 0; o >>= 1) {
            dm += __shfl_down_sync(FULL, dm, o);
            vm += __shfl_down_sync(FULL, vm, o);
            dc += __shfl_down_sync(FULL, dc, o);
            vc += __shfl_down_sync(FULL, vc, o);
        }
        if (lane == 0) s_e[bb] = dm / fmaxf(vm, 1.0f) + dc / fmaxf(vc, 1.0f);
    }
    __syncthreads();

    if (tid == 0) {
        float e[Bv];
        float m = 0.0f;
        #pragma unroll
        for (int i = 0; i < Bv; ++i) { e[i] = s_e[i]; m += e[i]; }
        m /= (float)Bv;
        float var = 0.0f;
        #pragma unroll
        for (int i = 0; i < Bv; ++i) { float dd = e[i] - m; var += dd * dd; }
        var /= (float)Bv;
        float sd = fmaxf(sqrtf(var), 1e-6f);
        float x[Bv], mx = -1e30f;
        #pragma unroll
        for (int i = 0; i < Bv; ++i) { x[i] = -(e[i] - m) / sd; mx = fmaxf(mx, x[i]); }
        float s = 0.0f;
        #pragma unroll
        for (int i = 0; i < Bv; ++i) { x[i] = expf(x[i] - mx); s += x[i]; }
        float s2 = 0.0f;
        #pragma unroll
        for (int i = 0; i < Bv; ++i) { float wv = x[i] / s; x[i] = wv; s2 += wv * wv; }
        #pragma unroll
        for (int i = 0; i < Bv; ++i) out[2 * Bv * TPv + i] = (float)Bv * x[i];
        out[2 * Bv * TPv + Bv] = 1.0f / s2;
    }
}

// ---------------------------------------------------------------------------

extern "C" void kernel_launch(void* const* d_in, const int* in_sizes, int n_in,
                              void* d_out, int out_size) {
    const float* f0   = (const float*)d_in[0];   // [B, TF]
    const float* attn = (const float*)d_in[1];   // [B, TP, TF2]
    const float* uv   = (const float*)d_in[2];   // [B, TP]
    float* out = (float*)d_out;                  // curv | mean | B*wts | ess

    mega_kernel<<<Bv * 32, 256>>>(f0, attn, uv, out);
}